// round 4
// baseline (speedup 1.0000x reference)
#include <cuda_runtime.h>
#include <cuda_bf16.h>
#include <math.h>

// ---------------- problem constants ----------------
#define TB      16
#define TN      4096
#define TLD     256
#define TH      8
#define TDH     64
#define TWIN    128
#define TINNER  512      // H*DH
#define TFF     1024
#define TDEPTH  4
#define TSLACK  50
#define TOKENS  (TB*TN)  // 65536
#define NWIN    (TN/TWIN) // 32

// weight-split sizes (bf16, K' = 3K)
#define SZ_QKV  (768*1536)
#define SZ_WOUT (1536*256)
#define SZ_W1   (768*1024)
#define SZ_W2   (3072*256)
#define LAYER_SZ (SZ_QKV + SZ_WOUT + SZ_W1 + SZ_W2)

#define GBM 128
#define GBN 128
#define GBK 64
#define G_SMEM ((GBM*GBK + GBK*GBN) * 2 * 2)   // two stages, bytes = 65536

// ---------------- scratch (static device allocations) ----------------
__device__ float g_h[(size_t)TOKENS*TLD];
__device__ float g_qkv[(size_t)TOKENS*3*TINNER];
__device__ __nv_bfloat16 g_ah [(size_t)TOKENS*3072];
__device__ __nv_bfloat16 g_ah2[(size_t)TOKENS*3072];
__device__ __nv_bfloat16 g_bw[(size_t)TDEPTH*LAYER_SZ];
__device__ float g_cos[TN*32];
__device__ float g_sin[TN*32];

// ---------------- helpers ----------------
__device__ __forceinline__ float blockSum256(float v) {
    __shared__ float sred[8];
    __syncthreads();
    #pragma unroll
    for (int o = 16; o > 0; o >>= 1) v += __shfl_down_sync(0xffffffffu, v, o);
    if ((threadIdx.x & 31) == 0) sred[threadIdx.x >> 5] = v;
    __syncthreads();
    if (threadIdx.x == 0) {
        float s = 0.f;
        #pragma unroll
        for (int i = 0; i < 8; i++) s += sred[i];
        sred[0] = s;
    }
    __syncthreads();
    return sred[0];
}

__device__ __forceinline__ void split2(float v, __nv_bfloat16& hi, __nv_bfloat16& lo) {
    hi = __float2bfloat16(v);
    lo = __float2bfloat16(v - __bfloat162float(hi));
}

__device__ __forceinline__ void cpasync16(void* dst, const void* src) {
    unsigned int d = (unsigned int)__cvta_generic_to_shared(dst);
    asm volatile("cp.async.cg.shared.global [%0], [%1], 16;\n" :: "r"(d), "l"(src));
}

__device__ __forceinline__ void ldsm_x4(unsigned int& r0, unsigned int& r1,
                                        unsigned int& r2, unsigned int& r3, unsigned int addr) {
    asm volatile("ldmatrix.sync.aligned.m8n8.x4.shared.b16 {%0,%1,%2,%3}, [%4];\n"
                 : "=r"(r0), "=r"(r1), "=r"(r2), "=r"(r3) : "r"(addr));
}
__device__ __forceinline__ void ldsm_x4t(unsigned int& r0, unsigned int& r1,
                                         unsigned int& r2, unsigned int& r3, unsigned int addr) {
    asm volatile("ldmatrix.sync.aligned.m8n8.x4.trans.shared.b16 {%0,%1,%2,%3}, [%4];\n"
                 : "=r"(r0), "=r"(r1), "=r"(r2), "=r"(r3) : "r"(addr));
}
__device__ __forceinline__ void mma16816(float* c, const unsigned int* a,
                                         unsigned int b0, unsigned int b1) {
    asm volatile("mma.sync.aligned.m16n8k16.row.col.f32.bf16.bf16.f32 "
                 "{%0,%1,%2,%3}, {%4,%5,%6,%7}, {%8,%9}, {%0,%1,%2,%3};\n"
                 : "+f"(c[0]), "+f"(c[1]), "+f"(c[2]), "+f"(c[3])
                 : "r"(a[0]), "r"(a[1]), "r"(a[2]), "r"(a[3]), "r"(b0), "r"(b1));
}

__device__ __forceinline__ void g_load_tile(__nv_bfloat16* As, __nv_bfloat16* Bs,
                                            const __nv_bfloat16* A, const __nv_bfloat16* B,
                                            int tid, int rowBase, int colBase,
                                            int k0, int K3, int N) {
    #pragma unroll
    for (int s = 0; s < 4; s++) {
        int i = s * 256 + tid;
        int r = i >> 3, c = i & 7;
        cpasync16(As + r * GBK + ((c ^ (r & 7)) << 3),
                  A + (size_t)(rowBase + r) * K3 + k0 + c * 8);
    }
    #pragma unroll
    for (int s = 0; s < 4; s++) {
        int i = s * 256 + tid;
        int r = i >> 4, c = i & 15;
        cpasync16(Bs + r * GBN + ((c ^ (r & 7)) << 3),
                  B + (size_t)(k0 + r) * N + colBase + c * 8);
    }
    asm volatile("cp.async.commit_group;\n");
}

// ---------------- small kernels ----------------
__global__ void embed_kernel(const float* __restrict__ x, const float* __restrict__ We,
                             const float* __restrict__ be, const float* __restrict__ pe) {
    int t = blockIdx.x, c = threadIdx.x;
    int n = t & (TN - 1);
    float x0 = x[2 * t], x1 = x[2 * t + 1];
    g_h[(size_t)t * TLD + c] = x0 * We[c] + x1 * We[TLD + c] + be[c] + pe[(size_t)n * TLD + c];
}

__global__ void ln_split_kernel(const float* __restrict__ in,
                                const float* __restrict__ g, const float* __restrict__ b) {
    int t = blockIdx.x, c = threadIdx.x;
    float v = in[(size_t)t * TLD + c];
    float mean = blockSum256(v) * (1.0f / TLD);
    float d = v - mean;
    float var = blockSum256(d * d) * (1.0f / TLD);
    float y = d * rsqrtf(var + 1e-5f) * g[c] + b[c];
    __nv_bfloat16 hi, lo;
    split2(y, hi, lo);
    size_t base = (size_t)t * 768;
    g_ah[base + c]       = hi;
    g_ah[base + 256 + c] = lo;
    g_ah[base + 512 + c] = hi;
}

__global__ void wsplit_kernel(const float* __restrict__ W, __nv_bfloat16* __restrict__ out,
                              int K, int N) {
    int idx = blockIdx.x * 256 + threadIdx.x;
    if (idx >= K * N) return;
    int k = idx / N, n = idx - k * N;
    __nv_bfloat16 hi, lo;
    split2(W[idx], hi, lo);
    out[(size_t)k * N + n]           = hi;
    out[(size_t)(K + k) * N + n]     = hi;
    out[(size_t)(2 * K + k) * N + n] = lo;
}

__global__ void rope_table_kernel() {
    int idx = blockIdx.x * 256 + threadIdx.x;
    int n = idx >> 5, i = idx & 31;
    double inv = exp(-(double)i * (9.210340371976184 / 32.0));
    double ang = (double)n * inv;
    g_cos[idx] = (float)cos(ang);
    g_sin[idx] = (float)sin(ang);
}

// ---------------- tensor-core GEMM ----------------
__global__ void __launch_bounds__(256) tgemm(const __nv_bfloat16* __restrict__ A,
                                             const __nv_bfloat16* __restrict__ B,
                                             const float* __restrict__ bias,
                                             float* __restrict__ C,
                                             __nv_bfloat16* __restrict__ S,
                                             int K3, int N, int epi) {
    extern __shared__ float dynsmem[];
    __nv_bfloat16* sm = reinterpret_cast<__nv_bfloat16*>(dynsmem);

    const int tid = threadIdx.x;
    const int lane = tid & 31, warp = tid >> 5;
    const int wm = warp >> 1, wn = warp & 1;
    const int rowBase = blockIdx.y * GBM, colBase = blockIdx.x * GBN;
    const int stageElems = GBM * GBK + GBK * GBN;

    float acc[2][8][4];
    #pragma unroll
    for (int a = 0; a < 2; a++)
        #pragma unroll
        for (int b = 0; b < 8; b++)
            #pragma unroll
            for (int c = 0; c < 4; c++) acc[a][b][c] = 0.f;

    const int NK = K3 / GBK;
    g_load_tile(sm, sm + GBM * GBK, A, B, tid, rowBase, colBase, 0, K3, N);

    const int mat = lane >> 3, lr = lane & 7;
    for (int kt = 0; kt < NK; kt++) {
        int cur = kt & 1;
        if (kt + 1 < NK) {
            __nv_bfloat16* nx = sm + (cur ^ 1) * stageElems;
            g_load_tile(nx, nx + GBM * GBK, A, B, tid, rowBase, colBase,
                        (kt + 1) * GBK, K3, N);
            asm volatile("cp.async.wait_group 1;\n");
        } else {
            asm volatile("cp.async.wait_group 0;\n");
        }
        __syncthreads();

        const __nv_bfloat16* As = sm + cur * stageElems;
        const __nv_bfloat16* Bs = As + GBM * GBK;
        unsigned int a_base = (unsigned int)__cvta_generic_to_shared(As);
        unsigned int b_base = (unsigned int)__cvta_generic_to_shared(Bs);

        #pragma unroll
        for (int kk = 0; kk < 4; kk++) {
            unsigned int a[2][4];
            #pragma unroll
            for (int mi = 0; mi < 2; mi++) {
                int r  = wm * 32 + mi * 16 + ((mat & 1) << 3) + lr;
                int ch = kk * 2 + (mat >> 1);
                unsigned int addr = a_base + (unsigned int)(r * GBK + ((ch ^ (r & 7)) << 3)) * 2;
                ldsm_x4(a[mi][0], a[mi][1], a[mi][2], a[mi][3], addr);
            }
            #pragma unroll
            for (int nj = 0; nj < 4; nj++) {
                int ni = wn * 8 + nj * 2 + (mat >> 1);
                int kr = kk * 16 + ((mat & 1) << 3) + lr;
                unsigned int addr = b_base + (unsigned int)(kr * GBN + ((ni ^ (kr & 7)) << 3)) * 2;
                unsigned int b0, b1, b2, b3;
                ldsm_x4t(b0, b1, b2, b3, addr);
                #pragma unroll
                for (int mi = 0; mi < 2; mi++) {
                    mma16816(acc[mi][nj * 2],     a[mi], b0, b1);
                    mma16816(acc[mi][nj * 2 + 1], a[mi], b2, b3);
                }
            }
        }
        __syncthreads();
    }

    const int qr = lane >> 2, qc = (lane & 3) * 2;
    #pragma unroll
    for (int mi = 0; mi < 2; mi++) {
        #pragma unroll
        for (int nt = 0; nt < 8; nt++) {
            int row0 = rowBase + wm * 32 + mi * 16 + qr;
            int col  = colBase + wn * 64 + nt * 8 + qc;
            float* cc = acc[mi][nt];
            #pragma unroll
            for (int half = 0; half < 2; half++) {
                int row = row0 + half * 8;
                #pragma unroll
                for (int j = 0; j < 2; j++) {
                    float v = cc[half * 2 + j];
                    int c2 = col + j;
                    size_t off = (size_t)row * N + c2;
                    if (epi == 0) {
                        C[off] = v;
                    } else if (epi == 1) {
                        C[off] += v;
                    } else if (epi == 2) {
                        v += bias[c2];
                        v = 0.5f * v * (1.0f + erff(v * 0.70710678118654752f));
                        __nv_bfloat16 hi, lo;
                        split2(v, hi, lo);
                        size_t sb = (size_t)row * (3 * (size_t)N);
                        S[sb + c2]         = hi;
                        S[sb + N + c2]     = lo;
                        S[sb + 2 * N + c2] = hi;
                    } else {
                        v += bias[c2];
                        C[off] += v;
                    }
                }
            }
        }
    }
}

// ---------------- local attention (v2: 2 lanes per query, RoPE fused) ----------
// grid (NWIN, TH, TB), 256 threads, 128KB dynamic smem.
// warp w handles queries w*16 .. w*16+15; lane pair (2j, 2j+1) = query w*16+j,
// lane&1 selects dim half (0: dims 0-31, 1: dims 32-63).
__global__ void __launch_bounds__(256) attn_kernel() {
    extern __shared__ float dynsmem[];
    float* Ks = dynsmem;             // 256 x 64
    float* Vs = dynsmem + 256 * 64;  // 256 x 64
    const int iw = blockIdx.x, hh = blockIdx.y, b = blockIdx.z;
    const int tid = threadIdx.x;
    const int lane = tid & 31, warp = tid >> 5;
    const int p = warp * 16 + (lane >> 1);   // query row 0..127
    const int half = lane & 1;               // dim half

    // load K (with rotary) and V tiles
    const int tbase = b * TN + (iw - 1) * TWIN;   // token of key jj=0
    for (int idx = tid; idx < 256 * 64; idx += 256) {
        int jj = idx >> 6, d = idx & 63;
        float kk = 0.f, vv = 0.f;
        if (iw > 0 || jj >= TWIN) {
            size_t tk = (size_t)(tbase + jj);
            int ntok = (int)(tk & (TN - 1));
            const float* kp = g_qkv + tk * (3 * TINNER) + TINNER + hh * 64;
            int i = d & 31;
            float c = g_cos[ntok * 32 + i];
            float s = g_sin[ntok * 32 + i];
            float k1 = kp[i], k2 = kp[i + 32];
            kk = (d < 32) ? (k1 * c - k2 * s) : (k2 * c + k1 * s);
            vv = g_qkv[tk * (3 * TINNER) + 2 * TINNER + hh * 64 + d];
        }
        Ks[idx] = kk;
        Vs[idx] = vv;
    }
    __syncthreads();

    // load this query's dims (with rotary), scaled
    const int t = b * TN + iw * TWIN + p;
    const int ntok = t & (TN - 1);
    const float* qp = g_qkv + (size_t)t * (3 * TINNER) + hh * 64;
    float q[32];
    #pragma unroll
    for (int j = 0; j < 32; j++) {
        float c = g_cos[ntok * 32 + j];
        float s = g_sin[ntok * 32 + j];
        float q1 = qp[j], q2 = qp[j + 32];
        float r = (half == 0) ? (q1 * c - q2 * s) : (q2 * c + q1 * s);
        q[j] = r * 0.125f;
    }

    float m = -1e30f, l = 0.f, acc[32];
    #pragma unroll
    for (int j = 0; j < 32; j++) acc[j] = 0.f;

    const int lo_b = (iw == 0) ? TWIN : p;
    const int hi_b = p + TWIN;
    for (int jj = lo_b; jj <= hi_b; jj++) {
        const float* kr = Ks + jj * 64 + half * 32;
        float partial = 0.f;
        #pragma unroll
        for (int j = 0; j < 32; j++) partial += q[j] * kr[j];
        float s = partial + __shfl_xor_sync(0xffffffffu, partial, 1);
        float mn = fmaxf(m, s);
        float corr = expf(m - mn);
        float w = expf(s - mn);
        l = l * corr + w;
        const float* vr = Vs + jj * 64 + half * 32;
        #pragma unroll
        for (int j = 0; j < 32; j++) acc[j] = acc[j] * corr + w * vr[j];
        m = mn;
    }
    float invl = 1.0f / l;
    size_t base = (size_t)t * 1536 + hh * 64 + half * 32;
    #pragma unroll
    for (int j = 0; j < 32; j++) {
        float v = acc[j] * invl;
        __nv_bfloat16 hi, lo;
        split2(v, hi, lo);
        g_ah[base + j]        = hi;
        g_ah[base + 512 + j]  = lo;
        g_ah[base + 1024 + j] = hi;
    }
}

// ---------------- final LN + logits ----------------
__global__ void final_kernel(const float* __restrict__ g, const float* __restrict__ bb,
                             const float* __restrict__ Wl, float* __restrict__ out) {
    int t = blockIdx.x, c = threadIdx.x;
    float v = g_h[(size_t)t * TLD + c];
    float mean = blockSum256(v) * (1.0f / TLD);
    float d = v - mean;
    float var = blockSum256(d * d) * (1.0f / TLD);
    float y = d * rsqrtf(var + 1e-5f) * g[c] + bb[c];
    float s = blockSum256(y * Wl[c]);
    if (c == 0) {
        int n = t & (TN - 1), b = t >> 12;
        if (n >= TSLACK && n < TN - TSLACK)
            out[b * (TN - 2 * TSLACK) + (n - TSLACK)] = s;
    }
}

// ---------------- host orchestration ----------------
extern "C" void kernel_launch(void* const* d_in, const int* in_sizes, int n_in,
                              void* d_out, int out_size) {
    const float* x         = (const float*)d_in[0];
    const float* W_exp     = (const float*)d_in[1];
    const float* b_exp     = (const float*)d_in[2];
    const float* pos_emb   = (const float*)d_in[3];
    const float* ln_attn_g = (const float*)d_in[4];
    const float* ln_attn_b = (const float*)d_in[5];
    const float* Wqkv      = (const float*)d_in[6];
    const float* Wout      = (const float*)d_in[7];
    const float* ln_ff_g   = (const float*)d_in[8];
    const float* ln_ff_b   = (const float*)d_in[9];
    const float* W1        = (const float*)d_in[10];
    const float* b1        = (const float*)d_in[11];
    const float* W2        = (const float*)d_in[12];
    const float* b2        = (const float*)d_in[13];
    const float* ln_f_g    = (const float*)d_in[14];
    const float* ln_f_b    = (const float*)d_in[15];
    const float* W_logits  = (const float*)d_in[16];
    float* out = (float*)d_out;

    void *ph, *pqkv, *pah, *pah2, *pbw;
    cudaGetSymbolAddress(&ph,   g_h);
    cudaGetSymbolAddress(&pqkv, g_qkv);
    cudaGetSymbolAddress(&pah,  g_ah);
    cudaGetSymbolAddress(&pah2, g_ah2);
    cudaGetSymbolAddress(&pbw,  g_bw);
    float* H   = (float*)ph;
    __nv_bfloat16* AH  = (__nv_bfloat16*)pah;
    __nv_bfloat16* AH2 = (__nv_bfloat16*)pah2;
    __nv_bfloat16* BW  = (__nv_bfloat16*)pbw;

    cudaFuncSetAttribute(attn_kernel, cudaFuncAttributeMaxDynamicSharedMemorySize, 131072);
    cudaFuncSetAttribute(tgemm, cudaFuncAttributeMaxDynamicSharedMemorySize, G_SMEM);

    for (int l = 0; l < TDEPTH; l++) {
        __nv_bfloat16* wb = BW + (size_t)l * LAYER_SZ;
        const float* Wqkv_l = Wqkv + (size_t)l * TLD * (3 * TINNER);
        const float* Wout_l = Wout + (size_t)l * TINNER * TLD;
        const float* W1_l   = W1   + (size_t)l * TLD * TFF;
        const float* W2_l   = W2   + (size_t)l * TFF * TLD;
        wsplit_kernel<<<(TLD * 3 * TINNER + 255) / 256, 256>>>(Wqkv_l, wb, TLD, 3 * TINNER);
        wsplit_kernel<<<(TINNER * TLD + 255) / 256, 256>>>(Wout_l, wb + SZ_QKV, TINNER, TLD);
        wsplit_kernel<<<(TLD * TFF + 255) / 256, 256>>>(W1_l, wb + SZ_QKV + SZ_WOUT, TLD, TFF);
        wsplit_kernel<<<(TFF * TLD + 255) / 256, 256>>>(W2_l, wb + SZ_QKV + SZ_WOUT + SZ_W1, TFF, TLD);
    }

    embed_kernel<<<TOKENS, 256>>>(x, W_exp, b_exp, pos_emb);
    rope_table_kernel<<<(TN * 32) / 256, 256>>>();

    for (int l = 0; l < TDEPTH; l++) {
        __nv_bfloat16* wb   = BW + (size_t)l * LAYER_SZ;
        __nv_bfloat16* Bqkv = wb;
        __nv_bfloat16* Bout = wb + SZ_QKV;
        __nv_bfloat16* B1w  = wb + SZ_QKV + SZ_WOUT;
        __nv_bfloat16* B2w  = wb + SZ_QKV + SZ_WOUT + SZ_W1;

        ln_split_kernel<<<TOKENS, 256>>>(H, ln_attn_g + l * TLD, ln_attn_b + l * TLD);
        tgemm<<<dim3((3 * TINNER) / GBN, TOKENS / GBM), 256, G_SMEM>>>(
            AH, Bqkv, (const float*)0, (float*)pqkv, (__nv_bfloat16*)0, 768, 3 * TINNER, 0);
        attn_kernel<<<dim3(NWIN, TH, TB), 256, 131072>>>();
        tgemm<<<dim3(TLD / GBN, TOKENS / GBM), 256, G_SMEM>>>(
            AH, Bout, (const float*)0, H, (__nv_bfloat16*)0, 1536, TLD, 1);
        ln_split_kernel<<<TOKENS, 256>>>(H, ln_ff_g + l * TLD, ln_ff_b + l * TLD);
        tgemm<<<dim3(TFF / GBN, TOKENS / GBM), 256, G_SMEM>>>(
            AH, B1w, b1 + l * TFF, (float*)0, AH2, 768, TFF, 2);
        tgemm<<<dim3(TLD / GBN, TOKENS / GBM), 256, G_SMEM>>>(
            AH2, B2w, b2 + l * TLD, H, (__nv_bfloat16*)0, 3072, TLD, 3);
    }

    final_kernel<<<TOKENS, 256>>>(ln_f_g, ln_f_b, W_logits, out);
}

// round 6
// speedup vs baseline: 2.3404x; 2.3404x over previous
#include <cuda_runtime.h>
#include <cuda_bf16.h>
#include <math.h>

// ---------------- problem constants ----------------
#define TB      16
#define TN      4096
#define TLD     256
#define TH      8
#define TDH     64
#define TWIN    128
#define TINNER  512      // H*DH
#define TFF     1024
#define TDEPTH  4
#define TSLACK  50
#define TOKENS  (TB*TN)  // 65536
#define NWIN    (TN/TWIN) // 32

// weight-split sizes (bf16, K' = 3K)
#define SZ_QKV  (768*1536)
#define SZ_WOUT (1536*256)
#define SZ_W1   (768*1024)
#define SZ_W2   (3072*256)
#define LAYER_SZ (SZ_QKV + SZ_WOUT + SZ_W1 + SZ_W2)
#define WELEMS_PER_LAYER (256*1536 + 512*256 + 256*1024 + 1024*256)  // 1048576

#define GBM 128
#define GBN 128
#define GBK 64
#define G_SMEM ((GBM*GBK + GBK*GBN) * 2 * 2)   // two stages, bytes = 65536

// ---------------- scratch (static device allocations) ----------------
__device__ float g_h[(size_t)TOKENS*TLD];
__device__ float g_qkv[(size_t)TOKENS*3*TINNER];
__device__ __nv_bfloat16 g_ah [(size_t)TOKENS*3072];
__device__ __nv_bfloat16 g_ah2[(size_t)TOKENS*3072];
__device__ __nv_bfloat16 g_bw[(size_t)TDEPTH*LAYER_SZ];
__device__ float g_cos[TN*32];
__device__ float g_sin[TN*32];

// ---------------- helpers ----------------
__device__ __forceinline__ float blockSum256(float v) {
    __shared__ float sred[8];
    __syncthreads();
    #pragma unroll
    for (int o = 16; o > 0; o >>= 1) v += __shfl_down_sync(0xffffffffu, v, o);
    if ((threadIdx.x & 31) == 0) sred[threadIdx.x >> 5] = v;
    __syncthreads();
    if (threadIdx.x == 0) {
        float s = 0.f;
        #pragma unroll
        for (int i = 0; i < 8; i++) s += sred[i];
        sred[0] = s;
    }
    __syncthreads();
    return sred[0];
}

__device__ __forceinline__ void split2(float v, __nv_bfloat16& hi, __nv_bfloat16& lo) {
    hi = __float2bfloat16(v);
    lo = __float2bfloat16(v - __bfloat162float(hi));
}

__device__ __forceinline__ void cpasync16(void* dst, const void* src) {
    unsigned int d = (unsigned int)__cvta_generic_to_shared(dst);
    asm volatile("cp.async.cg.shared.global [%0], [%1], 16;\n" :: "r"(d), "l"(src));
}

__device__ __forceinline__ void ldsm_x4(unsigned int& r0, unsigned int& r1,
                                        unsigned int& r2, unsigned int& r3, unsigned int addr) {
    asm volatile("ldmatrix.sync.aligned.m8n8.x4.shared.b16 {%0,%1,%2,%3}, [%4];\n"
                 : "=r"(r0), "=r"(r1), "=r"(r2), "=r"(r3) : "r"(addr));
}
__device__ __forceinline__ void ldsm_x4t(unsigned int& r0, unsigned int& r1,
                                         unsigned int& r2, unsigned int& r3, unsigned int addr) {
    asm volatile("ldmatrix.sync.aligned.m8n8.x4.trans.shared.b16 {%0,%1,%2,%3}, [%4];\n"
                 : "=r"(r0), "=r"(r1), "=r"(r2), "=r"(r3) : "r"(addr));
}
__device__ __forceinline__ void mma16816(float* c, const unsigned int* a,
                                         unsigned int b0, unsigned int b1) {
    asm volatile("mma.sync.aligned.m16n8k16.row.col.f32.bf16.bf16.f32 "
                 "{%0,%1,%2,%3}, {%4,%5,%6,%7}, {%8,%9}, {%0,%1,%2,%3};\n"
                 : "+f"(c[0]), "+f"(c[1]), "+f"(c[2]), "+f"(c[3])
                 : "r"(a[0]), "r"(a[1]), "r"(a[2]), "r"(a[3]), "r"(b0), "r"(b1));
}

__device__ __forceinline__ void g_load_tile(__nv_bfloat16* As, __nv_bfloat16* Bs,
                                            const __nv_bfloat16* A, const __nv_bfloat16* B,
                                            int tid, int rowBase, int colBase,
                                            int k0, int K3, int N) {
    #pragma unroll
    for (int s = 0; s < 4; s++) {
        int i = s * 256 + tid;
        int r = i >> 3, c = i & 7;
        cpasync16(As + r * GBK + ((c ^ (r & 7)) << 3),
                  A + (size_t)(rowBase + r) * K3 + k0 + c * 8);
    }
    #pragma unroll
    for (int s = 0; s < 4; s++) {
        int i = s * 256 + tid;
        int r = i >> 4, c = i & 15;
        cpasync16(Bs + r * GBN + ((c ^ (r & 7)) << 3),
                  B + (size_t)(k0 + r) * N + colBase + c * 8);
    }
    asm volatile("cp.async.commit_group;\n");
}

// ---------------- small kernels ----------------
__global__ void embed_kernel(const float* __restrict__ x, const float* __restrict__ We,
                             const float* __restrict__ be, const float* __restrict__ pe) {
    int t = blockIdx.x, c = threadIdx.x;
    int n = t & (TN - 1);
    float x0 = x[2 * t], x1 = x[2 * t + 1];
    g_h[(size_t)t * TLD + c] = x0 * We[c] + x1 * We[TLD + c] + be[c] + pe[(size_t)n * TLD + c];
}

__global__ void ln_split_kernel(const float* __restrict__ in,
                                const float* __restrict__ g, const float* __restrict__ b) {
    int t = blockIdx.x, c = threadIdx.x;
    float v = in[(size_t)t * TLD + c];
    float mean = blockSum256(v) * (1.0f / TLD);
    float d = v - mean;
    float var = blockSum256(d * d) * (1.0f / TLD);
    float y = d * rsqrtf(var + 1e-5f) * g[c] + b[c];
    __nv_bfloat16 hi, lo;
    split2(y, hi, lo);
    size_t base = (size_t)t * 768;
    g_ah[base + c]       = hi;
    g_ah[base + 256 + c] = lo;
    g_ah[base + 512 + c] = hi;
}

// split weights for TWO layers per launch (keeps launch count low so ncu's
// "-s 5" sampling lands on the first tgemm).
__global__ void wsplit2_kernel(const float* __restrict__ Wqkv, const float* __restrict__ Wout,
                               const float* __restrict__ W1, const float* __restrict__ W2,
                               int l0) {
    long long gidx = (long long)blockIdx.x * 256 + threadIdx.x;
    int l = l0 + (int)(gidx >> 20);              // WELEMS_PER_LAYER = 2^20
    int idx = (int)(gidx & (WELEMS_PER_LAYER - 1));

    const float* src;
    __nv_bfloat16* dst = g_bw + (size_t)l * LAYER_SZ;
    int K, N, local;
    if (idx < 256 * 1536) {
        src = Wqkv + (size_t)l * 256 * 1536;
        K = 256; N = 1536; local = idx;
    } else if (idx < 256 * 1536 + 512 * 256) {
        src = Wout + (size_t)l * 512 * 256;
        dst += SZ_QKV;
        K = 512; N = 256; local = idx - 256 * 1536;
    } else if (idx < 256 * 1536 + 512 * 256 + 256 * 1024) {
        src = W1 + (size_t)l * 256 * 1024;
        dst += SZ_QKV + SZ_WOUT;
        K = 256; N = 1024; local = idx - (256 * 1536 + 512 * 256);
    } else {
        src = W2 + (size_t)l * 1024 * 256;
        dst += SZ_QKV + SZ_WOUT + SZ_W1;
        K = 1024; N = 256; local = idx - (256 * 1536 + 512 * 256 + 256 * 1024);
    }
    int k = local / N, n = local - k * N;
    __nv_bfloat16 hi, lo;
    split2(src[local], hi, lo);
    dst[(size_t)k * N + n]           = hi;
    dst[(size_t)(K + k) * N + n]     = hi;
    dst[(size_t)(2 * K + k) * N + n] = lo;
}

__global__ void rope_table_kernel() {
    int idx = blockIdx.x * 256 + threadIdx.x;
    int n = idx >> 5, i = idx & 31;
    double inv = exp(-(double)i * (9.210340371976184 / 32.0));
    double ang = (double)n * inv;
    g_cos[idx] = (float)cos(ang);
    g_sin[idx] = (float)sin(ang);
}

// ---------------- tensor-core GEMM ----------------
__global__ void __launch_bounds__(256) tgemm(const __nv_bfloat16* __restrict__ A,
                                             const __nv_bfloat16* __restrict__ B,
                                             const float* __restrict__ bias,
                                             float* __restrict__ C,
                                             __nv_bfloat16* __restrict__ S,
                                             int K3, int N, int epi) {
    extern __shared__ float dynsmem[];
    __nv_bfloat16* sm = reinterpret_cast<__nv_bfloat16*>(dynsmem);

    const int tid = threadIdx.x;
    const int lane = tid & 31, warp = tid >> 5;
    const int wm = warp >> 1, wn = warp & 1;
    const int rowBase = blockIdx.y * GBM, colBase = blockIdx.x * GBN;
    const int stageElems = GBM * GBK + GBK * GBN;

    float acc[2][8][4];
    #pragma unroll
    for (int a = 0; a < 2; a++)
        #pragma unroll
        for (int b = 0; b < 8; b++)
            #pragma unroll
            for (int c = 0; c < 4; c++) acc[a][b][c] = 0.f;

    const int NK = K3 / GBK;
    g_load_tile(sm, sm + GBM * GBK, A, B, tid, rowBase, colBase, 0, K3, N);

    const int mat = lane >> 3, lr = lane & 7;
    for (int kt = 0; kt < NK; kt++) {
        int cur = kt & 1;
        if (kt + 1 < NK) {
            __nv_bfloat16* nx = sm + (cur ^ 1) * stageElems;
            g_load_tile(nx, nx + GBM * GBK, A, B, tid, rowBase, colBase,
                        (kt + 1) * GBK, K3, N);
            asm volatile("cp.async.wait_group 1;\n");
        } else {
            asm volatile("cp.async.wait_group 0;\n");
        }
        __syncthreads();

        const __nv_bfloat16* As = sm + cur * stageElems;
        const __nv_bfloat16* Bs = As + GBM * GBK;
        unsigned int a_base = (unsigned int)__cvta_generic_to_shared(As);
        unsigned int b_base = (unsigned int)__cvta_generic_to_shared(Bs);

        #pragma unroll
        for (int kk = 0; kk < 4; kk++) {
            unsigned int a[2][4];
            #pragma unroll
            for (int mi = 0; mi < 2; mi++) {
                int r  = wm * 32 + mi * 16 + ((mat & 1) << 3) + lr;
                int ch = kk * 2 + (mat >> 1);
                unsigned int addr = a_base + (unsigned int)(r * GBK + ((ch ^ (r & 7)) << 3)) * 2;
                ldsm_x4(a[mi][0], a[mi][1], a[mi][2], a[mi][3], addr);
            }
            #pragma unroll
            for (int nj = 0; nj < 4; nj++) {
                int ni = wn * 8 + nj * 2 + (mat >> 1);
                int kr = kk * 16 + ((mat & 1) << 3) + lr;
                unsigned int addr = b_base + (unsigned int)(kr * GBN + ((ni ^ (kr & 7)) << 3)) * 2;
                unsigned int b0, b1, b2, b3;
                ldsm_x4t(b0, b1, b2, b3, addr);
                #pragma unroll
                for (int mi = 0; mi < 2; mi++) {
                    mma16816(acc[mi][nj * 2],     a[mi], b0, b1);
                    mma16816(acc[mi][nj * 2 + 1], a[mi], b2, b3);
                }
            }
        }
        __syncthreads();
    }

    const int qr = lane >> 2, qc = (lane & 3) * 2;
    #pragma unroll
    for (int mi = 0; mi < 2; mi++) {
        #pragma unroll
        for (int nt = 0; nt < 8; nt++) {
            int row0 = rowBase + wm * 32 + mi * 16 + qr;
            int col  = colBase + wn * 64 + nt * 8 + qc;
            float* cc = acc[mi][nt];
            #pragma unroll
            for (int half = 0; half < 2; half++) {
                int row = row0 + half * 8;
                #pragma unroll
                for (int j = 0; j < 2; j++) {
                    float v = cc[half * 2 + j];
                    int c2 = col + j;
                    size_t off = (size_t)row * N + c2;
                    if (epi == 0) {
                        C[off] = v;
                    } else if (epi == 1) {
                        C[off] += v;
                    } else if (epi == 2) {
                        v += bias[c2];
                        v = 0.5f * v * (1.0f + erff(v * 0.70710678118654752f));
                        __nv_bfloat16 hi, lo;
                        split2(v, hi, lo);
                        size_t sb = (size_t)row * (3 * (size_t)N);
                        S[sb + c2]         = hi;
                        S[sb + N + c2]     = lo;
                        S[sb + 2 * N + c2] = hi;
                    } else {
                        v += bias[c2];
                        C[off] += v;
                    }
                }
            }
        }
    }
}

// ---------------- local attention (v3: 2 lanes/query, warp-uniform loop) ------
// grid (NWIN, TH, TB), 256 threads, 128KB dynamic smem.
// warp w handles queries w*16 .. w*16+15; lane pair (2j,2j+1) = query w*16+j;
// lane&1 selects dim half. Loop bounds are UNIFORM per warp; invalid keys are
// masked via s=-1e30 so the lane-pair shuffle always executes converged.
__global__ void __launch_bounds__(256) attn_kernel() {
    extern __shared__ float dynsmem[];
    float* Ks = dynsmem;             // 256 x 64
    float* Vs = dynsmem + 256 * 64;  // 256 x 64
    const int iw = blockIdx.x, hh = blockIdx.y, b = blockIdx.z;
    const int tid = threadIdx.x;
    const int lane = tid & 31, warp = tid >> 5;
    const int p = warp * 16 + (lane >> 1);   // query row 0..127
    const int half = lane & 1;               // dim half

    // load K (with rotary) and V tiles
    const int tbase = b * TN + (iw - 1) * TWIN;   // token of key jj=0
    for (int idx = tid; idx < 256 * 64; idx += 256) {
        int jj = idx >> 6, d = idx & 63;
        float kk = 0.f, vv = 0.f;
        if (iw > 0 || jj >= TWIN) {
            size_t tk = (size_t)(tbase + jj);
            int ntok = (int)(tk & (TN - 1));
            const float* kp = g_qkv + tk * (3 * TINNER) + TINNER + hh * 64;
            int i = d & 31;
            float c = g_cos[ntok * 32 + i];
            float s = g_sin[ntok * 32 + i];
            float k1 = kp[i], k2 = kp[i + 32];
            kk = (d < 32) ? (k1 * c - k2 * s) : (k2 * c + k1 * s);
            vv = g_qkv[tk * (3 * TINNER) + 2 * TINNER + hh * 64 + d];
        }
        Ks[idx] = kk;
        Vs[idx] = vv;
    }
    __syncthreads();

    // load this query's dims (with rotary), scaled
    const int t = b * TN + iw * TWIN + p;
    const int ntok = t & (TN - 1);
    const float* qp = g_qkv + (size_t)t * (3 * TINNER) + hh * 64;
    float q[32];
    #pragma unroll
    for (int j = 0; j < 32; j++) {
        float c = g_cos[ntok * 32 + j];
        float s = g_sin[ntok * 32 + j];
        float q1 = qp[j], q2 = qp[j + 32];
        float r = (half == 0) ? (q1 * c - q2 * s) : (q2 * c + q1 * s);
        q[j] = r * 0.125f;
    }

    float m = -1e30f, l = 0.f, acc[32];
    #pragma unroll
    for (int j = 0; j < 32; j++) acc[j] = 0.f;

    // per-lane valid range
    const int lo_b = (iw == 0) ? TWIN : p;
    const int hi_b = p + TWIN;
    // warp-uniform range (union over the warp's 16 queries)
    const int lo_w = (iw == 0) ? TWIN : warp * 16;
    const int hi_w = warp * 16 + 15 + TWIN;

    for (int jj = lo_w; jj <= hi_w; jj++) {
        const float* kr = Ks + jj * 64 + half * 32;
        float partial = 0.f;
        #pragma unroll
        for (int j = 0; j < 32; j++) partial += q[j] * kr[j];
        float s = partial + __shfl_xor_sync(0xffffffffu, partial, 1);
        if (jj < lo_b || jj > hi_b) s = -1e30f;   // masked key: weight 0
        float mn = fmaxf(m, s);
        float corr = expf(m - mn);
        float w = expf(s - mn);
        l = l * corr + w;
        const float* vr = Vs + jj * 64 + half * 32;
        #pragma unroll
        for (int j = 0; j < 32; j++) acc[j] = acc[j] * corr + w * vr[j];
        m = mn;
    }
    float invl = 1.0f / l;
    size_t base = (size_t)t * 1536 + hh * 64 + half * 32;
    #pragma unroll
    for (int j = 0; j < 32; j++) {
        float v = acc[j] * invl;
        __nv_bfloat16 hi, lo;
        split2(v, hi, lo);
        g_ah[base + j]        = hi;
        g_ah[base + 512 + j]  = lo;
        g_ah[base + 1024 + j] = hi;
    }
}

// ---------------- final LN + logits ----------------
__global__ void final_kernel(const float* __restrict__ g, const float* __restrict__ bb,
                             const float* __restrict__ Wl, float* __restrict__ out) {
    int t = blockIdx.x, c = threadIdx.x;
    float v = g_h[(size_t)t * TLD + c];
    float mean = blockSum256(v) * (1.0f / TLD);
    float d = v - mean;
    float var = blockSum256(d * d) * (1.0f / TLD);
    float y = d * rsqrtf(var + 1e-5f) * g[c] + bb[c];
    float s = blockSum256(y * Wl[c]);
    if (c == 0) {
        int n = t & (TN - 1), b = t >> 12;
        if (n >= TSLACK && n < TN - TSLACK)
            out[b * (TN - 2 * TSLACK) + (n - TSLACK)] = s;
    }
}

// ---------------- host orchestration ----------------
extern "C" void kernel_launch(void* const* d_in, const int* in_sizes, int n_in,
                              void* d_out, int out_size) {
    const float* x         = (const float*)d_in[0];
    const float* W_exp     = (const float*)d_in[1];
    const float* b_exp     = (const float*)d_in[2];
    const float* pos_emb   = (const float*)d_in[3];
    const float* ln_attn_g = (const float*)d_in[4];
    const float* ln_attn_b = (const float*)d_in[5];
    const float* Wqkv      = (const float*)d_in[6];
    const float* Wout      = (const float*)d_in[7];
    const float* ln_ff_g   = (const float*)d_in[8];
    const float* ln_ff_b   = (const float*)d_in[9];
    const float* W1        = (const float*)d_in[10];
    const float* b1        = (const float*)d_in[11];
    const float* W2        = (const float*)d_in[12];
    const float* b2        = (const float*)d_in[13];
    const float* ln_f_g    = (const float*)d_in[14];
    const float* ln_f_b    = (const float*)d_in[15];
    const float* W_logits  = (const float*)d_in[16];
    float* out = (float*)d_out;

    void *ph, *pqkv, *pah, *pah2, *pbw;
    cudaGetSymbolAddress(&ph,   g_h);
    cudaGetSymbolAddress(&pqkv, g_qkv);
    cudaGetSymbolAddress(&pah,  g_ah);
    cudaGetSymbolAddress(&pah2, g_ah2);
    cudaGetSymbolAddress(&pbw,  g_bw);
    float* H   = (float*)ph;
    __nv_bfloat16* AH  = (__nv_bfloat16*)pah;
    __nv_bfloat16* AH2 = (__nv_bfloat16*)pah2;
    __nv_bfloat16* BW  = (__nv_bfloat16*)pbw;

    cudaFuncSetAttribute(attn_kernel, cudaFuncAttributeMaxDynamicSharedMemorySize, 131072);
    cudaFuncSetAttribute(tgemm, cudaFuncAttributeMaxDynamicSharedMemorySize, G_SMEM);

    // launches 1-2: weight splits (two layers each)
    wsplit2_kernel<<<2 * WELEMS_PER_LAYER / 256, 256>>>(Wqkv, Wout, W1, W2, 0);
    wsplit2_kernel<<<2 * WELEMS_PER_LAYER / 256, 256>>>(Wqkv, Wout, W1, W2, 2);
    // launches 3-4
    embed_kernel<<<TOKENS, 256>>>(x, W_exp, b_exp, pos_emb);
    rope_table_kernel<<<(TN * 32) / 256, 256>>>();

    for (int l = 0; l < TDEPTH; l++) {
        __nv_bfloat16* wb   = BW + (size_t)l * LAYER_SZ;
        __nv_bfloat16* Bqkv = wb;
        __nv_bfloat16* Bout = wb + SZ_QKV;
        __nv_bfloat16* B1w  = wb + SZ_QKV + SZ_WOUT;
        __nv_bfloat16* B2w  = wb + SZ_QKV + SZ_WOUT + SZ_W1;

        // launch 5 (l=0): ln_split; launch 6 (l=0): tgemm QKV  <-- ncu -s 5 target
        ln_split_kernel<<<TOKENS, 256>>>(H, ln_attn_g + l * TLD, ln_attn_b + l * TLD);
        tgemm<<<dim3((3 * TINNER) / GBN, TOKENS / GBM), 256, G_SMEM>>>(
            AH, Bqkv, (const float*)0, (float*)pqkv, (__nv_bfloat16*)0, 768, 3 * TINNER, 0);
        attn_kernel<<<dim3(NWIN, TH, TB), 256, 131072>>>();
        tgemm<<<dim3(TLD / GBN, TOKENS / GBM), 256, G_SMEM>>>(
            AH, Bout, (const float*)0, H, (__nv_bfloat16*)0, 1536, TLD, 1);
        ln_split_kernel<<<TOKENS, 256>>>(H, ln_ff_g + l * TLD, ln_ff_b + l * TLD);
        tgemm<<<dim3(TFF / GBN, TOKENS / GBM), 256, G_SMEM>>>(
            AH, B1w, b1 + l * TFF, (float*)0, AH2, 768, TFF, 2);
        tgemm<<<dim3(TLD / GBN, TOKENS / GBM), 256, G_SMEM>>>(
            AH2, B2w, b2 + l * TLD, H, (__nv_bfloat16*)0, 3072, TLD, 3);
    }

    final_kernel<<<TOKENS, 256>>>(ln_f_g, ln_f_b, W_logits, out);
}